// round 1
// baseline (speedup 1.0000x reference)
#include <cuda_runtime.h>

#define Nn 50000
#define Ee 800000
#define INF_ 256
#define Hh 128
#define OUTc 2

// ---------------- device scratch (static, no allocations) ----------------
__device__ float g_xs[Nn * Hh];
__device__ float g_xd[Nn * Hh];
__device__ float g_lin[Nn * Hh];
__device__ float g_h[Nn * Hh];
__device__ float g_xs2[Nn * OUTc];
__device__ float g_xd2[Nn * OUTc];
__device__ float g_linf[Nn * OUTc];
__device__ int   g_deg[Nn];
__device__ int   g_rowptr[Nn + 1];
__device__ int   g_cursor[Nn];
__device__ int   g_srcs[Ee];
__device__ int   g_bsums[64];

__device__ __forceinline__ float lrelu(float v) { return v > 0.f ? v : 0.2f * v; }

__device__ __forceinline__ float wsum(float v) {
#pragma unroll
    for (int o = 16; o; o >>= 1) v += __shfl_xor_sync(0xffffffffu, v, o);
    return v;
}

// ---------------- CSR build ----------------
__global__ void k_zero() {
    int i = blockIdx.x * blockDim.x + threadIdx.x;
    if (i < Nn) g_deg[i] = 0;
}

__global__ void k_count(const int* __restrict__ ei) {
    int e = blockIdx.x * blockDim.x + threadIdx.x;
    if (e < Ee) atomicAdd(&g_deg[ei[Ee + e]], 1);
}

__global__ void k_scan1() {
    __shared__ int sh[1024];
    int t = threadIdx.x;
    int i = blockIdx.x * 1024 + t;
    int v = (i < Nn) ? g_deg[i] : 0;
    sh[t] = v;
    __syncthreads();
#pragma unroll
    for (int off = 1; off < 1024; off <<= 1) {
        int x = (t >= off) ? sh[t - off] : 0;
        __syncthreads();
        sh[t] += x;
        __syncthreads();
    }
    if (i < Nn) g_rowptr[i + 1] = sh[t];
    if (t == 1023) g_bsums[blockIdx.x] = sh[t];
}

__global__ void k_scan2(int nb) {
    if (threadIdx.x == 0 && blockIdx.x == 0) {
        int run = 0;
        for (int b = 0; b < nb; b++) { int v = g_bsums[b]; g_bsums[b] = run; run += v; }
    }
}

__global__ void k_scan3() {
    int i = blockIdx.x * blockDim.x + threadIdx.x;
    if (i < Nn) g_rowptr[i + 1] += g_bsums[i >> 10];
    if (i == 0) g_rowptr[0] = 0;
}

__global__ void k_cursor() {
    int i = blockIdx.x * blockDim.x + threadIdx.x;
    if (i < Nn) g_cursor[i] = g_rowptr[i];
}

__global__ void k_fill(const int* __restrict__ ei) {
    int e = blockIdx.x * blockDim.x + threadIdx.x;
    if (e < Ee) {
        int d = ei[Ee + e];
        int p = atomicAdd(&g_cursor[d], 1);
        g_srcs[p] = ei[e];
    }
}

// ---------------- fused GEMM: C(xs|xd|lin) = A @ (Wl|Wr|Wlin) ----------------
// BM=128, BN=64, BK=16, 256 threads, thread tile 8x4.
// blockIdx.y in 0..5: groups {0,1}->Wl->g_xs, {2,3}->Wr->g_xd, {4,5}->Wlin->g_lin(+lb)
__global__ void k_gemm(const float* __restrict__ A, int K,
                       const float* __restrict__ Wl, const float* __restrict__ Wr,
                       const float* __restrict__ Wlin, const float* __restrict__ lb,
                       int reluA) {
    __shared__ float As[16][132];
    __shared__ float Bs[16][68];
    const int bc  = blockIdx.y;
    const int grp = bc >> 1;
    const int cb  = (bc & 1) * 64;
    const float* W = (grp == 0) ? Wl : (grp == 1) ? Wr : Wlin;
    const bool isLin = (grp == 2);
    const int row0 = blockIdx.x * 128;
    const int t  = threadIdx.x;
    const int tx = t & 15, ty = t >> 4;
    const bool doRelu = isLin && (reluA != 0);

    float acc[8][4];
#pragma unroll
    for (int r = 0; r < 8; r++)
#pragma unroll
        for (int q = 0; q < 4; q++) acc[r][q] = 0.f;

    for (int k0 = 0; k0 < K; k0 += 16) {
#pragma unroll
        for (int j = 0; j < 2; j++) {
            int idx = t + j * 256;
            int r = idx >> 2, kk = (idx & 3) << 2;
            int grow = row0 + r;
            float4 a;
            if (grow < Nn) a = *(const float4*)(A + (size_t)grow * K + k0 + kk);
            else           a = make_float4(0.f, 0.f, 0.f, 0.f);
            if (doRelu) {
                a.x = fmaxf(a.x, 0.f); a.y = fmaxf(a.y, 0.f);
                a.z = fmaxf(a.z, 0.f); a.w = fmaxf(a.w, 0.f);
            }
            As[kk + 0][r] = a.x; As[kk + 1][r] = a.y;
            As[kk + 2][r] = a.z; As[kk + 3][r] = a.w;
        }
        {
            int r = t >> 4, c = (t & 15) << 2;
            *(float4*)&Bs[r][c] = *(const float4*)(W + (size_t)(k0 + r) * Hh + cb + c);
        }
        __syncthreads();
#pragma unroll
        for (int k = 0; k < 16; k++) {
            float4 b4 = *(float4*)&Bs[k][tx << 2];
            float4 a0 = *(float4*)&As[k][ty << 3];
            float4 a1 = *(float4*)&As[k][(ty << 3) + 4];
            float av[8] = {a0.x, a0.y, a0.z, a0.w, a1.x, a1.y, a1.z, a1.w};
#pragma unroll
            for (int r = 0; r < 8; r++) {
                acc[r][0] += av[r] * b4.x;
                acc[r][1] += av[r] * b4.y;
                acc[r][2] += av[r] * b4.z;
                acc[r][3] += av[r] * b4.w;
            }
        }
        __syncthreads();
    }

    float4 bias = make_float4(0.f, 0.f, 0.f, 0.f);
    if (isLin) bias = *(const float4*)(lb + cb + (tx << 2));
    float* Out = (grp == 0) ? g_xs : (grp == 1) ? g_xd : g_lin;
#pragma unroll
    for (int r = 0; r < 8; r++) {
        int grow = row0 + (ty << 3) + r;
        if (grow < Nn) {
            float4 v = make_float4(acc[r][0] + bias.x, acc[r][1] + bias.y,
                                   acc[r][2] + bias.z, acc[r][3] + bias.w);
            *(float4*)(Out + (size_t)grow * Hh + cb + (tx << 2)) = v;
        }
    }
}

// ---------------- warp-per-node online-softmax aggregation (H=128) ----------------
__global__ void k_agg(const float* __restrict__ att, const float* __restrict__ bias,
                      float* __restrict__ out, int doRelu) {
    int gw = (blockIdx.x * blockDim.x + threadIdx.x) >> 5;
    int lane = threadIdx.x & 31;
    if (gw >= Nn) return;
    const int i = gw;
    const int fo = lane << 2;

    float4 xd4 = *(const float4*)&g_xd[(size_t)i * Hh + fo];
    float4 at4 = *(const float4*)(att + fo);

    float m = -1e30f, sv = 0.f;
    float4 acc = make_float4(0.f, 0.f, 0.f, 0.f);
    int j = g_rowptr[i], end = g_rowptr[i + 1];
    for (; j < end; j++) {
        int s = g_srcs[j];
        float4 xs4 = *(const float4*)&g_xs[(size_t)s * Hh + fo];
        float p = lrelu(xs4.x + xd4.x) * at4.x + lrelu(xs4.y + xd4.y) * at4.y
                + lrelu(xs4.z + xd4.z) * at4.z + lrelu(xs4.w + xd4.w) * at4.w;
        float e = wsum(p);
        if (e > m) {
            float c = __expf(m - e);
            sv *= c; acc.x *= c; acc.y *= c; acc.z *= c; acc.w *= c;
            m = e;
        }
        float w = __expf(e - m);
        sv += w;
        acc.x += w * xs4.x; acc.y += w * xs4.y;
        acc.z += w * xs4.z; acc.w += w * xs4.w;
    }
    float inv = 1.f / (sv + 1e-16f);
    float4 lin4 = *(const float4*)&g_lin[(size_t)i * Hh + fo];
    float4 b4   = *(const float4*)(bias + fo);
    float4 r = make_float4(acc.x * inv + b4.x + lin4.x,
                           acc.y * inv + b4.y + lin4.y,
                           acc.z * inv + b4.z + lin4.z,
                           acc.w * inv + b4.w + lin4.w);
    if (doRelu) {
        r.x = fmaxf(r.x, 0.f); r.y = fmaxf(r.y, 0.f);
        r.z = fmaxf(r.z, 0.f); r.w = fmaxf(r.w, 0.f);
    }
    *(float4*)(out + (size_t)i * Hh + fo) = r;
}

// ---------------- final layer: emb @ (cf_Wl|cf_Wr|lf_W), K=128, Nout=2 each --------
__global__ void k_ftrans(const float* __restrict__ emb,
                         const float* __restrict__ Wl, const float* __restrict__ Wr,
                         const float* __restrict__ Wlin, const float* __restrict__ lb) {
    __shared__ float sW[Hh * 6];
    int t = threadIdx.x;
    for (int idx = t; idx < Hh * 6; idx += blockDim.x) {
        int f = idx / 6, c = idx % 6;
        sW[idx] = (c < 2) ? Wl[f * 2 + c] : (c < 4) ? Wr[f * 2 + c - 2] : Wlin[f * 2 + c - 4];
    }
    __syncthreads();
    int warp = t >> 5, lane = t & 31;
    int i = blockIdx.x * 8 + warp;
    if (i >= Nn) return;
    float4 ev = *(const float4*)(emb + (size_t)i * Hh + (lane << 2));
    float r0 = 0, r1 = 0, r2 = 0, r3 = 0, r4 = 0, r5 = 0;
    float vv[4] = {ev.x, ev.y, ev.z, ev.w};
#pragma unroll
    for (int q = 0; q < 4; q++) {
        int f = (lane << 2) + q;
        float v = vv[q], vr = fmaxf(v, 0.f);
        const float* w = &sW[f * 6];
        r0 += v * w[0]; r1 += v * w[1];
        r2 += v * w[2]; r3 += v * w[3];
        r4 += vr * w[4]; r5 += vr * w[5];
    }
    r0 = wsum(r0); r1 = wsum(r1); r2 = wsum(r2);
    r3 = wsum(r3); r4 = wsum(r4); r5 = wsum(r5);
    if (lane == 0) {
        g_xs2[2 * i] = r0; g_xs2[2 * i + 1] = r1;
        g_xd2[2 * i] = r2; g_xd2[2 * i + 1] = r3;
        g_linf[2 * i] = r4 + lb[0]; g_linf[2 * i + 1] = r5 + lb[1];
    }
}

__global__ void k_aggf(const float* __restrict__ att, const float* __restrict__ bias,
                       float* __restrict__ out) {
    int i = blockIdx.x * blockDim.x + threadIdx.x;
    if (i >= Nn) return;
    float a0 = att[0], a1 = att[1];
    float xd0 = g_xd2[2 * i], xd1 = g_xd2[2 * i + 1];
    float m = -1e30f, sv = 0.f, ac0 = 0.f, ac1 = 0.f;
    int end = g_rowptr[i + 1];
    for (int j = g_rowptr[i]; j < end; j++) {
        int s = g_srcs[j];
        float xs0 = g_xs2[2 * s], xs1 = g_xs2[2 * s + 1];
        float e = lrelu(xs0 + xd0) * a0 + lrelu(xs1 + xd1) * a1;
        if (e > m) {
            float c = __expf(m - e);
            sv *= c; ac0 *= c; ac1 *= c;
            m = e;
        }
        float w = __expf(e - m);
        sv += w; ac0 += w * xs0; ac1 += w * xs1;
    }
    float inv = 1.f / (sv + 1e-16f);
    out[2 * i]     = ac0 * inv + bias[0] + g_linf[2 * i];
    out[2 * i + 1] = ac1 * inv + bias[1] + g_linf[2 * i + 1];
}

// ---------------- launch ----------------
extern "C" void kernel_launch(void* const* d_in, const int* in_sizes, int n_in,
                              void* d_out, int out_size) {
    const float* x      = (const float*)d_in[0];
    const int*   ei     = (const int*)d_in[1];
    const float* c0_Wl  = (const float*)d_in[2];
    const float* c0_Wr  = (const float*)d_in[3];
    const float* c0_att = (const float*)d_in[4];
    const float* c0_b   = (const float*)d_in[5];
    const float* c1_Wl  = (const float*)d_in[6];
    const float* c1_Wr  = (const float*)d_in[7];
    const float* c1_att = (const float*)d_in[8];
    const float* c1_b   = (const float*)d_in[9];
    const float* cf_Wl  = (const float*)d_in[10];
    const float* cf_Wr  = (const float*)d_in[11];
    const float* cf_att = (const float*)d_in[12];
    const float* cf_b   = (const float*)d_in[13];
    const float* l0_W   = (const float*)d_in[14];
    const float* l0_b   = (const float*)d_in[15];
    const float* l1_W   = (const float*)d_in[16];
    const float* l1_b   = (const float*)d_in[17];
    const float* lf_W   = (const float*)d_in[18];
    const float* lf_b   = (const float*)d_in[19];

    float* out = (float*)d_out;
    float* emb = out + (size_t)Nn * OUTc;

    float* hbuf = nullptr;
    cudaGetSymbolAddress((void**)&hbuf, g_h);

    const int NB_SCAN = (Nn + 1023) / 1024;

    // CSR build (per launch; same result every time -> deterministic work)
    k_zero  <<<(Nn + 255) / 256, 256>>>();
    k_count <<<(Ee + 255) / 256, 256>>>(ei);
    k_scan1 <<<NB_SCAN, 1024>>>();
    k_scan2 <<<1, 32>>>(NB_SCAN);
    k_scan3 <<<(Nn + 255) / 256, 256>>>();
    k_cursor<<<(Nn + 255) / 256, 256>>>();
    k_fill  <<<(Ee + 255) / 256, 256>>>(ei);

    dim3 gg((Nn + 127) / 128, 6);

    // layer 0: h = relu(gat(x) + relu(x)@l0_W + l0_b)
    k_gemm<<<gg, 256>>>(x, INF_, c0_Wl, c0_Wr, l0_W, l0_b, 1);
    k_agg <<<(Nn + 7) / 8, 256>>>(c0_att, c0_b, hbuf, 1);

    // layer 1: emb = gat(h) + h@l1_W + l1_b   (relu(h)==h since h>=0)
    k_gemm<<<gg, 256>>>(hbuf, Hh, c1_Wl, c1_Wr, l1_W, l1_b, 1);
    k_agg <<<(Nn + 7) / 8, 256>>>(c1_att, c1_b, emb, 0);

    // final: out = gat(emb) + relu(emb)@lf_W + lf_b
    k_ftrans<<<(Nn + 7) / 8, 256>>>(emb, cf_Wl, cf_Wr, lf_W, lf_b);
    k_aggf  <<<(Nn + 255) / 256, 256>>>(cf_att, cf_b, out);
}